// round 16
// baseline (speedup 1.0000x reference)
#include <cuda_runtime.h>
#include <cstdint>
#include <math.h>

// ===== Problem dims =====
#define BB   16384
#define K1   784
#define HH   1024
#define NW   32          // HH/32 packed words per row
#define NOUT 10
#define NPART 128        // bgemm partial blocks (grid.y = BB/128)
#define NPART1 128       // gemm1 partial blocks (grid.y = BB/128)

// ===== Scratch (device globals) =====
__device__ float    g_h[(size_t)BB*HH];
__device__ unsigned g_nv[BB*NW];
__device__ unsigned g_act[BB*NW];
__device__ float    g_sW1[K1*HH];           // sign(W1)^T, [k][n]
__device__ unsigned g_w2[HH*NW];
__device__ unsigned g_w3[HH*NW];
__device__ unsigned g_w4[NOUT*NW];
__device__ double   g_part[NPART][2*HH];
__device__ float    g_muf[HH];
__device__ float    g_rf[HH];
__device__ unsigned g_sel[NW];
__device__ unsigned g_mb[NW];
__device__ float    g_lutf[27];

// packed f32x2 fma: halves round independently (rn) -> each half's chain
// is bit-identical to scalar FFMA in the same order.
__device__ __forceinline__ unsigned long long fma2(unsigned long long a,
                                                   unsigned long long b,
                                                   unsigned long long c) {
    unsigned long long d;
    asm("fma.rn.f32x2 %0, %1, %2, %3;" : "=l"(d) : "l"(a), "l"(b), "l"(c));
    return d;
}
__device__ __forceinline__ unsigned long long dup2(float a) {
    unsigned long long d;
    asm("mov.b64 %0, {%1, %1};" : "=l"(d) : "r"(__float_as_uint(a)));
    return d;
}
__device__ __forceinline__ void kadd(float v, float& s, float& c) {
    float y = __fsub_rn(v, c);
    float t = __fadd_rn(s, y);
    c = __fsub_rn(__fsub_rn(t, s), y);
    s = t;
}

// ===================================================================
// Flip-threshold LUT (exact vs fp64 path; see R4 derivation)
// ===================================================================
__global__ void k_mklut() {
    int m = threadIdx.x;          // 0..26
    float t;
    if (m <= 25) {
        float x = (float)(2 * m);
        float q2 = (x * x) / 50.0f;
        double prob = 0.5 * exp(-(double)q2);
        t = (float)prob;
        if ((double)t < prob) t = __int_as_float(__float_as_int(t) + 1);
    } else t = -1.0f;
    g_lutf[m] = t;
}

// sign(W1)^T via smem tile transpose
__global__ void k_signW1(const float* __restrict__ W1) {
    __shared__ float tile[32][33];
    int k0 = blockIdx.x * 32, n0 = blockIdx.y * 32;
    int tx = threadIdx.x, ty = threadIdx.y;      // (32, 8)
#pragma unroll
    for (int r = 0; r < 32; r += 8) {
        int n = n0 + ty + r, k = k0 + tx;
        float w = (k < K1) ? W1[(size_t)n * K1 + k] : 0.f;
        tile[ty + r][tx] = (w > 0.f) ? 1.f : ((w < 0.f) ? -1.f : 0.f);
    }
    __syncthreads();
#pragma unroll
    for (int r = 0; r < 32; r += 8) {
        int k = k0 + ty + r, n = n0 + tx;
        if (k < K1) g_sW1[(size_t)k * HH + n] = tile[tx][ty + r];
    }
}

// Single kernel packs W2, W3, W4 sign bits
#define W2_ELEMS (HH*HH)
#define W4_ELEMS (NOUT*HH)
__global__ void k_packAll(const float* __restrict__ W2,
                          const float* __restrict__ W3,
                          const float* __restrict__ W4) {
    int idx = blockIdx.x * 256 + threadIdx.x;
    const float* W; unsigned* dst; int off;
    if (idx < W2_ELEMS)               { W = W2; dst = g_w2; off = 0; }
    else if (idx < 2 * W2_ELEMS)      { W = W3; dst = g_w3; off = W2_ELEMS; }
    else                              { W = W4; dst = g_w4; off = 2 * W2_ELEMS; }
    int li = idx - off;
    bool pos = (idx < 2 * W2_ELEMS + W4_ELEMS) ? (W[li] > 0.f) : false;
    unsigned bal = __ballot_sync(0xffffffffu, pos);
    if ((threadIdx.x & 31) == 0 && idx < 2 * W2_ELEMS + W4_ELEMS) dst[li >> 5] = bal;
}

// ===================================================================
// Layer 1 SGEMM: 128x128 CTA tile, 128 threads (4 warps), 16x8/thread.
// Warp tile = 32 rows x 128 cols -> IDENTICAL per-warp LDS pattern to the
// measured-best R9/R13 config, but 2 CTAs/SM (regs 30.5K, smem 32KB per
// CTA) so barrier bubbles in one CTA are filled by the other.
// Per-output chain: one accumulator, k ascending -> bit-identical.
// ===================================================================
__global__ __launch_bounds__(128, 2) void k_gemm1(const float* __restrict__ X) {
    __shared__ union {
        struct { float As[2][16][128]; float Bs[2][16][128]; } g;   // 32 KB
        struct { float s[8][128]; float c[8][128];
                 float q[8][128]; float cq[8][128]; } st;           // 16 KB
    } sm;
    int bn0 = blockIdx.x * 128;
    int bm0 = blockIdx.y * 128;
    int tid = threadIdx.x;
    int ty = tid >> 4, tx = tid & 15;    // ty 0..7 (16 rows each), tx 0..15 (8 cols)

    // A loader: thread owns row tid, 16 k-floats per tile (4 float4)
    const float* aptr = &X[(size_t)(bm0 + tid) * K1];
    // B loader: row = tid>>3 (0..15), cols (tid&7)*16 .. +15 (4 float4)
    int brow = tid >> 3, bcol = (tid & 7) * 16;
    const float* bptr = &g_sW1[(size_t)brow * HH + bn0 + bcol];

    unsigned long long acc2[16][4];
#pragma unroll
    for (int i = 0; i < 16; i++)
#pragma unroll
        for (int q = 0; q < 4; q++) acc2[i][q] = 0ULL;

    float4 av[4], bv[4];
#pragma unroll
    for (int i = 0; i < 4; i++) av[i] = *(const float4*)(aptr + 4 * i);
#pragma unroll
    for (int i = 0; i < 4; i++) bv[i] = *(const float4*)(bptr + 4 * i);
    {
#pragma unroll
        for (int i = 0; i < 4; i++) {
            sm.g.As[0][4*i + 0][tid] = av[i].x;
            sm.g.As[0][4*i + 1][tid] = av[i].y;
            sm.g.As[0][4*i + 2][tid] = av[i].z;
            sm.g.As[0][4*i + 3][tid] = av[i].w;
        }
#pragma unroll
        for (int i = 0; i < 4; i++)
            *(float4*)&sm.g.Bs[0][brow][bcol + 4 * i] = bv[i];
    }
    __syncthreads();

    int buf = 0;
    for (int kt = 16; kt <= K1; kt += 16) {
        bool more = (kt < K1);
        if (more) {
#pragma unroll
            for (int i = 0; i < 4; i++) av[i] = *(const float4*)(aptr + kt + 4 * i);
#pragma unroll
            for (int i = 0; i < 4; i++) bv[i] = *(const float4*)(bptr + (size_t)kt * HH + 4 * i);
        }
#pragma unroll
        for (int k = 0; k < 16; k++) {
            float4 a0 = *(const float4*)&sm.g.As[buf][k][ty * 16];
            float4 a1 = *(const float4*)&sm.g.As[buf][k][ty * 16 + 4];
            float4 a2 = *(const float4*)&sm.g.As[buf][k][ty * 16 + 8];
            float4 a3 = *(const float4*)&sm.g.As[buf][k][ty * 16 + 12];
            ulonglong2 b01 = *(const ulonglong2*)&sm.g.Bs[buf][k][tx * 8];
            ulonglong2 b23 = *(const ulonglong2*)&sm.g.Bs[buf][k][tx * 8 + 4];
            unsigned long long bq[4] = {b01.x, b01.y, b23.x, b23.y};
            float a[16] = {a0.x, a0.y, a0.z, a0.w, a1.x, a1.y, a1.z, a1.w,
                           a2.x, a2.y, a2.z, a2.w, a3.x, a3.y, a3.z, a3.w};
#pragma unroll
            for (int i = 0; i < 16; i++) {
                unsigned long long ai = dup2(a[i]);
#pragma unroll
                for (int q = 0; q < 4; q++)
                    acc2[i][q] = fma2(ai, bq[q], acc2[i][q]);
            }
        }
        if (more) {
            int nb = buf ^ 1;
#pragma unroll
            for (int i = 0; i < 4; i++) {
                sm.g.As[nb][4*i + 0][tid] = av[i].x;
                sm.g.As[nb][4*i + 1][tid] = av[i].y;
                sm.g.As[nb][4*i + 2][tid] = av[i].z;
                sm.g.As[nb][4*i + 3][tid] = av[i].w;
            }
#pragma unroll
            for (int i = 0; i < 4; i++)
                *(float4*)&sm.g.Bs[nb][brow][bcol + 4 * i] = bv[i];
            __syncthreads();
            buf = nb;
        }
    }

    // Store h + per-thread Kahan column stats (16 rows each, ascending i)
    float ss[8] = {0,0,0,0,0,0,0,0}, sc[8] = {0,0,0,0,0,0,0,0};
    float qs[8] = {0,0,0,0,0,0,0,0}, qc[8] = {0,0,0,0,0,0,0,0};
#pragma unroll
    for (int i = 0; i < 16; i++) {
        unsigned long long* p =
            (unsigned long long*)&g_h[(size_t)(bm0 + ty * 16 + i) * HH + bn0 + tx * 8];
        *(ulonglong2*)p       = make_ulonglong2(acc2[i][0], acc2[i][1]);
        *(ulonglong2*)(p + 2) = make_ulonglong2(acc2[i][2], acc2[i][3]);
#pragma unroll
        for (int q = 0; q < 4; q++) {
            float2 v2 = *(float2*)&acc2[i][q];
            kadd(v2.x, ss[2*q],   sc[2*q]);
            kadd(__fmul_rn(v2.x, v2.x), qs[2*q],   qc[2*q]);
            kadd(v2.y, ss[2*q+1], sc[2*q+1]);
            kadd(__fmul_rn(v2.y, v2.y), qs[2*q+1], qc[2*q+1]);
        }
    }
    __syncthreads();   // all As/Bs reads done; safe to reuse smem
#pragma unroll
    for (int j = 0; j < 8; j++) {
        int col = tx * 8 + j;
        sm.st.s[ty][col]  = ss[j];
        sm.st.c[ty][col]  = sc[j];
        sm.st.q[ty][col]  = qs[j];
        sm.st.cq[ty][col] = qc[j];
    }
    __syncthreads();
    // 128 threads, one column each; fixed ty order 0..7
    {
        double sd = 0, qd = 0;
#pragma unroll
        for (int t = 0; t < 8; t++) {
            sd += (double)sm.st.s[t][tid] - (double)sm.st.c[t][tid];
            qd += (double)sm.st.q[t][tid] - (double)sm.st.cq[t][tid];
        }
        g_part[blockIdx.y][bn0 + tid]      = sd;
        g_part[blockIdx.y][HH + bn0 + tid] = qd;
    }
}

// 16 blocks x 64 threads; per-column serial p-loop (p ascending) -> exact.
__global__ void k_reduce1() {
    int c = blockIdx.x * 64 + threadIdx.x;
    double s = 0, sq = 0;
    for (int p = 0; p < NPART1; p++) { s += g_part[p][c]; sq += g_part[p][HH + c]; }
    double mu = s / (double)BB;
    double var = sq / (double)BB - mu * mu;
    g_muf[c] = (float)mu;
    g_rf[c]  = (float)(1.0 / sqrt(var + 1e-5));
}

__global__ void k_pack1(const float* __restrict__ gv, const float* __restrict__ bv) {
    int idx = blockIdx.x * 256 + threadIdx.x;
    int c = idx & (HH - 1);
    float h = g_h[idx];
    float z = __fadd_rn(__fmul_rn(__fmul_rn(__fsub_rn(h, g_muf[c]), g_rf[c]), gv[c]), bv[c]);
    unsigned bal = __ballot_sync(0xffffffffu, z > 0.f);
    if ((threadIdx.x & 31) == 0) g_act[idx >> 5] = bal;
}

// ===================================================================
// Fused binary GEMM + noisy_binarize + bit-pack + column-sums (exact int)
// ===================================================================
__global__ __launch_bounds__(256) void k_bgemm_fused(int which, const float* __restrict__ U) {
    __shared__ unsigned As[32][128];
    __shared__ unsigned Ws[32][128];
    __shared__ float lut[27];
    __shared__ unsigned char sbits[128][16];
    __shared__ int icol[128][17];

    const unsigned* __restrict__ Wb = (which == 0) ? g_w2 : g_w3;
    int bn0 = blockIdx.x * 128;
    int bm0 = blockIdx.y * 128;
    int tid = threadIdx.x;
    int ty = tid >> 4, tx = tid & 15;

    if (tid < 27) lut[tid] = g_lutf[tid];

#pragma unroll
    for (int i = 0; i < 4; i++) {
        int p = tid * 4 + i;
        int r = p >> 3, c4 = (p & 7) << 2;
        uint4 av = *(const uint4*)&g_act[(size_t)(bm0 + r) * NW + c4];
        As[c4 + 0][r] = av.x; As[c4 + 1][r] = av.y;
        As[c4 + 2][r] = av.z; As[c4 + 3][r] = av.w;
        uint4 wv = *(const uint4*)&Wb[(size_t)(bn0 + r) * NW + c4];
        Ws[c4 + 0][r] = wv.x; Ws[c4 + 1][r] = wv.y;
        Ws[c4 + 2][r] = wv.z; Ws[c4 + 3][r] = wv.w;
    }
    __syncthreads();

    int acc[8][8];
#pragma unroll
    for (int i = 0; i < 8; i++)
#pragma unroll
        for (int j = 0; j < 8; j++) acc[i][j] = 0;

    for (int w = 0; w < 32; w += 2) {
        unsigned a0[8], b0[8], a1[8], b1[8];
#pragma unroll
        for (int i = 0; i < 8; i++) { a0[i] = As[w][ty * 8 + i]; a1[i] = As[w + 1][ty * 8 + i]; }
#pragma unroll
        for (int j = 0; j < 8; j++) { b0[j] = Ws[w][tx * 8 + j]; b1[j] = Ws[w + 1][tx * 8 + j]; }
#pragma unroll
        for (int i = 0; i < 8; i++)
#pragma unroll
            for (int j = 0; j < 8; j++)
                acc[i][j] += __popc(a0[i] ^ b0[j]) + __popc(a1[i] ^ b1[j]);
    }

    int csum[8];
#pragma unroll
    for (int j = 0; j < 8; j++) csum[j] = 0;
#pragma unroll
    for (int i = 0; i < 8; i++) {
        int rowg = bm0 + ty * 8 + i;
        float4 u0 = *(const float4*)&U[(size_t)rowg * HH + bn0 + tx * 8];
        float4 u1 = *(const float4*)&U[(size_t)rowg * HH + bn0 + tx * 8 + 4];
        float uu[8] = {u0.x, u0.y, u0.z, u0.w, u1.x, u1.y, u1.z, u1.w};
        unsigned byte = 0;
#pragma unroll
        for (int j = 0; j < 8; j++) {
            int cnt = acc[i][j];
            int hs = 512 - cnt;                 // h/2
            int m = (hs < 0) ? -hs : hs;
            if (m > 26) m = 26;
            bool pos = (hs > 0) ^ (uu[j] < lut[m]);
            byte |= (pos ? 1u : 0u) << j;
            csum[j] += pos ? 1 : -1;
        }
        sbits[ty * 8 + i][tx] = (unsigned char)byte;
    }
#pragma unroll
    for (int j = 0; j < 8; j++) icol[tx * 8 + j][ty] = csum[j];
    __syncthreads();

#pragma unroll
    for (int v = 0; v < 2; v++) {
        int wi = tid * 2 + v;
        int row = wi >> 2, w = wi & 3;
        unsigned word = *(const unsigned*)&sbits[row][w * 4];
        g_nv[(size_t)(bm0 + row) * NW + blockIdx.x * 4 + w] = word;
    }
    if (tid < 128) {
        int s = 0;
#pragma unroll
        for (int t = 0; t < 16; t++) s += icol[tid][t];
        g_part[blockIdx.y][bn0 + tid] = (double)s;
    }
}

// Parallelized BN-LUT: 32 blocks x 256 thr; integer partials -> exact.
__global__ void k_lut(const float* __restrict__ gv, const float* __restrict__ bv) {
    __shared__ double sh[8][32];
    int c0 = blockIdx.x * 32;
    int t = threadIdx.x;
    int col = t & 31, slice = t >> 5;
    double s = 0;
    for (int p = slice; p < NPART; p += 8) s += g_part[p][c0 + col];
    sh[slice][col] = s;
    __syncthreads();
    if (t < 32) {
        double tot = 0;
#pragma unroll
        for (int s2 = 0; s2 < 8; s2++) tot += sh[s2][t];
        int c = c0 + t;
        double mu = tot / (double)BB;
        double r = 1.0 / sqrt(1.0 - mu * mu + 1e-5);
        double zp = (( 1.0 - mu) * r) * (double)gv[c] + (double)bv[c];
        double zm = ((-1.0 - mu) * r) * (double)gv[c] + (double)bv[c];
        unsigned pb = __ballot_sync(0xffffffffu, zp > 0.0);
        unsigned mb = __ballot_sync(0xffffffffu, zm > 0.0);
        if (t == 0) {
            g_sel[blockIdx.x] = pb ^ mb;
            g_mb[blockIdx.x]  = mb;
        }
    }
}

__global__ void k_apply() {
    int i = blockIdx.x * 256 + threadIdx.x;
    int w = i & (NW - 1);
    g_act[i] = (g_nv[i] & g_sel[w]) ^ g_mb[w];
}

__global__ __launch_bounds__(256) void k_out(float* __restrict__ outp) {
    __shared__ unsigned As[256][33];
    __shared__ unsigned W4s[NOUT][NW];
    int r0 = blockIdx.x * 256;
    int t = threadIdx.x;
#pragma unroll
    for (int i = 0; i < 32; i++) {
        int p = t + 256 * i;
        As[p >> 5][p & 31] = g_act[(size_t)r0 * NW + p];
    }
    for (int i = t; i < NOUT * NW; i += 256) ((unsigned*)W4s)[i] = g_w4[i];
    __syncthreads();
#pragma unroll
    for (int o = 0; o < NOUT; o++) {
        int cnt = 0;
#pragma unroll
        for (int w = 0; w < NW; w += 2)
            cnt += __popc(As[t][w] ^ W4s[o][w]) + __popc(As[t][w + 1] ^ W4s[o][w + 1]);
        outp[(size_t)(r0 + t) * NOUT + o] = (float)(HH - 2 * cnt);
    }
}

// ===================================================================
extern "C" void kernel_launch(void* const* d_in, const int* in_sizes, int n_in,
                              void* d_out, int out_size) {
    const float* x  = (const float*)d_in[0];
    const float* u2 = (const float*)d_in[1];
    const float* u3 = (const float*)d_in[2];
    const float* W1 = (const float*)d_in[3];
    const float* W2 = (const float*)d_in[4];
    const float* W3 = (const float*)d_in[5];
    const float* W4 = (const float*)d_in[6];
    const float* g1 = (const float*)d_in[7];
    const float* b1 = (const float*)d_in[8];
    const float* g2 = (const float*)d_in[9];
    const float* b2 = (const float*)d_in[10];
    const float* g3 = (const float*)d_in[11];
    const float* b3 = (const float*)d_in[12];
    float* out = (float*)d_out;

    k_mklut<<<1, 27>>>();
    {
        dim3 tb(32, 8), tg((K1 + 31) / 32, HH / 32);
        k_signW1<<<tg, tb>>>(W1);
    }
    k_packAll<<<(2 * W2_ELEMS + W4_ELEMS + 255) / 256, 256>>>(W2, W3, W4);

    // Layer 1: 128x128 tiles, 128 threads, 2 CTAs/SM -> grid (8, 128)
    dim3 g1grid(HH / 128, BB / 128);
    k_gemm1<<<g1grid, 128>>>(x);
    k_reduce1<<<HH / 64, 64>>>();
    k_pack1<<<(BB * HH) / 256, 256>>>(g1, b1);

    dim3 ggrid(HH / 128, BB / 128);
    // Layer 2
    k_bgemm_fused<<<ggrid, 256>>>(0, u2);
    k_lut<<<NW, 256>>>(g2, b2);
    k_apply<<<(BB * NW) / 256, 256>>>();

    // Layer 3
    k_bgemm_fused<<<ggrid, 256>>>(1, u3);
    k_lut<<<NW, 256>>>(g3, b3);
    k_apply<<<(BB * NW) / 256, 256>>>();

    // Output layer
    k_out<<<BB / 256, 256>>>(out);
}

// round 17
// speedup vs baseline: 1.0173x; 1.0173x over previous
#include <cuda_runtime.h>
#include <cstdint>
#include <math.h>

// ===== Problem dims =====
#define BB   16384
#define K1   784
#define HH   1024
#define NW   32          // HH/32 packed words per row
#define NOUT 10
#define NPART 128        // bgemm partial blocks (grid.y = BB/128)
#define NPART1 64        // gemm1 partial blocks (grid.y = BB/256)

// ===== Scratch (device globals) =====
__device__ float    g_h[(size_t)BB*HH];
__device__ unsigned g_nv[BB*NW];
__device__ unsigned g_act[BB*NW];           // layer-1 packed activations
__device__ float    g_sW1[K1*HH];           // sign(W1)^T, [k][n]
__device__ unsigned g_w2[HH*NW];
__device__ unsigned g_w3[HH*NW];
__device__ unsigned g_w4[NOUT*NW];
__device__ double   g_part[NPART][2*HH];
__device__ float    g_muf[HH];
__device__ float    g_rf[HH];
__device__ unsigned g_sel[NW];
__device__ unsigned g_mb[NW];
__device__ float    g_lutf[27];

// packed f32x2 fma: halves round independently (rn) -> each half's chain
// is bit-identical to scalar FFMA in the same order.
__device__ __forceinline__ unsigned long long fma2(unsigned long long a,
                                                   unsigned long long b,
                                                   unsigned long long c) {
    unsigned long long d;
    asm("fma.rn.f32x2 %0, %1, %2, %3;" : "=l"(d) : "l"(a), "l"(b), "l"(c));
    return d;
}
__device__ __forceinline__ unsigned long long dup2(float a) {
    unsigned long long d;
    asm("mov.b64 %0, {%1, %1};" : "=l"(d) : "r"(__float_as_uint(a)));
    return d;
}
__device__ __forceinline__ void kadd(float v, float& s, float& c) {
    float y = __fsub_rn(v, c);
    float t = __fadd_rn(s, y);
    c = __fsub_rn(__fsub_rn(t, s), y);
    s = t;
}

// sign(W1)^T via smem tile transpose
__global__ void k_signW1(const float* __restrict__ W1) {
    __shared__ float tile[32][33];
    int k0 = blockIdx.x * 32, n0 = blockIdx.y * 32;
    int tx = threadIdx.x, ty = threadIdx.y;      // (32, 8)
#pragma unroll
    for (int r = 0; r < 32; r += 8) {
        int n = n0 + ty + r, k = k0 + tx;
        float w = (k < K1) ? W1[(size_t)n * K1 + k] : 0.f;
        tile[ty + r][tx] = (w > 0.f) ? 1.f : ((w < 0.f) ? -1.f : 0.f);
    }
    __syncthreads();
#pragma unroll
    for (int r = 0; r < 32; r += 8) {
        int k = k0 + ty + r, n = n0 + tx;
        if (k < K1) g_sW1[(size_t)k * HH + n] = tile[tx][ty + r];
    }
}

// Packs W2, W3, W4 sign bits; block 0 also builds the flip-threshold LUT
// (t[m] = smallest fp32 >= 0.5*exp(-((2m)^2/50)); exact vs fp64 compare).
#define W2_ELEMS (HH*HH)
#define W4_ELEMS (NOUT*HH)
__global__ void k_packAll(const float* __restrict__ W2,
                          const float* __restrict__ W3,
                          const float* __restrict__ W4) {
    if (blockIdx.x == 0 && threadIdx.x < 27) {
        int m = threadIdx.x;
        float t;
        if (m <= 25) {
            float x = (float)(2 * m);
            float q2 = (x * x) / 50.0f;
            double prob = 0.5 * exp(-(double)q2);
            t = (float)prob;
            if ((double)t < prob) t = __int_as_float(__float_as_int(t) + 1);
        } else t = -1.0f;
        g_lutf[m] = t;
    }
    int idx = blockIdx.x * 256 + threadIdx.x;
    const float* W; unsigned* dst; int off;
    if (idx < W2_ELEMS)               { W = W2; dst = g_w2; off = 0; }
    else if (idx < 2 * W2_ELEMS)      { W = W3; dst = g_w3; off = W2_ELEMS; }
    else                              { W = W4; dst = g_w4; off = 2 * W2_ELEMS; }
    int li = idx - off;
    bool pos = (idx < 2 * W2_ELEMS + W4_ELEMS) ? (W[li] > 0.f) : false;
    unsigned bal = __ballot_sync(0xffffffffu, pos);
    if ((threadIdx.x & 31) == 0 && idx < 2 * W2_ELEMS + W4_ELEMS) dst[li >> 5] = bal;
}

// ===================================================================
// Layer 1 SGEMM: R13 configuration, FROZEN (5 geometries tested; this is
// the measured optimum ~620us). 256x128 CTA, 256 thr, 16x8/thread, BK=16,
// double-buffered f32x2. Per-output chain bit-identical. Fused BN1 stats.
// ===================================================================
__global__ __launch_bounds__(256, 1) void k_gemm1(const float* __restrict__ X) {
    __shared__ union {
        struct { float As[2][16][256]; float Bs[2][16][128]; } g;   // 48 KB
        struct { float s[16][128]; float c[16][128];
                 float q[16][128]; float cq[16][128]; } st;         // 32 KB
    } sm;
    int bn0 = blockIdx.x * 128;
    int bm0 = blockIdx.y * 256;
    int tid = threadIdx.x;
    int ty = tid >> 4, tx = tid & 15;

    const float* aptr = &X[(size_t)(bm0 + tid) * K1];
    const float* bptr = &g_sW1[(size_t)ty * HH + bn0 + tx * 8];

    unsigned long long acc2[16][4];
#pragma unroll
    for (int i = 0; i < 16; i++)
#pragma unroll
        for (int q = 0; q < 4; q++) acc2[i][q] = 0ULL;

    float4 av[4], bv0, bv1;
#pragma unroll
    for (int i = 0; i < 4; i++) av[i] = *(const float4*)(aptr + 4 * i);
    bv0 = *(const float4*)bptr;
    bv1 = *(const float4*)(bptr + 4);
    {
#pragma unroll
        for (int i = 0; i < 4; i++) {
            sm.g.As[0][4*i + 0][tid] = av[i].x;
            sm.g.As[0][4*i + 1][tid] = av[i].y;
            sm.g.As[0][4*i + 2][tid] = av[i].z;
            sm.g.As[0][4*i + 3][tid] = av[i].w;
        }
        *(float4*)&sm.g.Bs[0][ty][tx * 8]     = bv0;
        *(float4*)&sm.g.Bs[0][ty][tx * 8 + 4] = bv1;
    }
    __syncthreads();

    int buf = 0;
    for (int kt = 16; kt <= K1; kt += 16) {
        bool more = (kt < K1);
        if (more) {
#pragma unroll
            for (int i = 0; i < 4; i++) av[i] = *(const float4*)(aptr + kt + 4 * i);
            bv0 = *(const float4*)(bptr + (size_t)kt * HH);
            bv1 = *(const float4*)(bptr + (size_t)kt * HH + 4);
        }
#pragma unroll
        for (int k = 0; k < 16; k++) {
            float4 a0 = *(const float4*)&sm.g.As[buf][k][ty * 16];
            float4 a1 = *(const float4*)&sm.g.As[buf][k][ty * 16 + 4];
            float4 a2 = *(const float4*)&sm.g.As[buf][k][ty * 16 + 8];
            float4 a3 = *(const float4*)&sm.g.As[buf][k][ty * 16 + 12];
            ulonglong2 b01 = *(const ulonglong2*)&sm.g.Bs[buf][k][tx * 8];
            ulonglong2 b23 = *(const ulonglong2*)&sm.g.Bs[buf][k][tx * 8 + 4];
            unsigned long long bq[4] = {b01.x, b01.y, b23.x, b23.y};
            float a[16] = {a0.x, a0.y, a0.z, a0.w, a1.x, a1.y, a1.z, a1.w,
                           a2.x, a2.y, a2.z, a2.w, a3.x, a3.y, a3.z, a3.w};
#pragma unroll
            for (int i = 0; i < 16; i++) {
                unsigned long long ai = dup2(a[i]);
#pragma unroll
                for (int q = 0; q < 4; q++)
                    acc2[i][q] = fma2(ai, bq[q], acc2[i][q]);
            }
        }
        if (more) {
            int nb = buf ^ 1;
#pragma unroll
            for (int i = 0; i < 4; i++) {
                sm.g.As[nb][4*i + 0][tid] = av[i].x;
                sm.g.As[nb][4*i + 1][tid] = av[i].y;
                sm.g.As[nb][4*i + 2][tid] = av[i].z;
                sm.g.As[nb][4*i + 3][tid] = av[i].w;
            }
            *(float4*)&sm.g.Bs[nb][ty][tx * 8]     = bv0;
            *(float4*)&sm.g.Bs[nb][ty][tx * 8 + 4] = bv1;
            __syncthreads();
            buf = nb;
        }
    }

    float ss[8] = {0,0,0,0,0,0,0,0}, sc[8] = {0,0,0,0,0,0,0,0};
    float qs[8] = {0,0,0,0,0,0,0,0}, qc[8] = {0,0,0,0,0,0,0,0};
#pragma unroll
    for (int i = 0; i < 16; i++) {
        unsigned long long* p =
            (unsigned long long*)&g_h[(size_t)(bm0 + ty * 16 + i) * HH + bn0 + tx * 8];
        *(ulonglong2*)p       = make_ulonglong2(acc2[i][0], acc2[i][1]);
        *(ulonglong2*)(p + 2) = make_ulonglong2(acc2[i][2], acc2[i][3]);
#pragma unroll
        for (int q = 0; q < 4; q++) {
            float2 v2 = *(float2*)&acc2[i][q];
            kadd(v2.x, ss[2*q],   sc[2*q]);
            kadd(__fmul_rn(v2.x, v2.x), qs[2*q],   qc[2*q]);
            kadd(v2.y, ss[2*q+1], sc[2*q+1]);
            kadd(__fmul_rn(v2.y, v2.y), qs[2*q+1], qc[2*q+1]);
        }
    }
    __syncthreads();
#pragma unroll
    for (int j = 0; j < 8; j++) {
        int col = tx * 8 + j;
        sm.st.s[ty][col]  = ss[j];
        sm.st.c[ty][col]  = sc[j];
        sm.st.q[ty][col]  = qs[j];
        sm.st.cq[ty][col] = qc[j];
    }
    __syncthreads();
    if (tid < 128) {
        double sd = 0, qd = 0;
#pragma unroll
        for (int t = 0; t < 16; t++) {
            sd += (double)sm.st.s[t][tid] - (double)sm.st.c[t][tid];
            qd += (double)sm.st.q[t][tid] - (double)sm.st.cq[t][tid];
        }
        g_part[blockIdx.y][bn0 + tid]      = sd;
        g_part[blockIdx.y][HH + bn0 + tid] = qd;
    }
}

// 16 blocks x 64 threads; per-column serial p-loop (p ascending) -> exact.
__global__ void k_reduce1() {
    int c = blockIdx.x * 64 + threadIdx.x;
    double s = 0, sq = 0;
    for (int p = 0; p < NPART1; p++) { s += g_part[p][c]; sq += g_part[p][HH + c]; }
    double mu = s / (double)BB;
    double var = sq / (double)BB - mu * mu;
    g_muf[c] = (float)mu;
    g_rf[c]  = (float)(1.0 / sqrt(var + 1e-5));
}

__global__ void k_pack1(const float* __restrict__ gv, const float* __restrict__ bv) {
    int idx = blockIdx.x * 256 + threadIdx.x;
    int c = idx & (HH - 1);
    float h = g_h[idx];
    float z = __fadd_rn(__fmul_rn(__fmul_rn(__fsub_rn(h, g_muf[c]), g_rf[c]), gv[c]), bv[c]);
    unsigned bal = __ballot_sync(0xffffffffu, z > 0.f);
    if ((threadIdx.x & 31) == 0) g_act[idx >> 5] = bal;
}

// ===================================================================
// Fused binary GEMM + noisy_binarize + bit-pack + column-sums (exact int).
// useLut=1: A-source is g_nv with BN-LUT (sel/mb) applied on load —
// replaces the old k_apply pass bit-identically.
// ===================================================================
__global__ __launch_bounds__(256) void k_bgemm_fused(int which, const float* __restrict__ U,
                                                     int useLut) {
    __shared__ unsigned As[32][128];
    __shared__ unsigned Ws[32][128];
    __shared__ float lut[27];
    __shared__ unsigned ssel[NW], smb[NW];
    __shared__ unsigned char sbits[128][16];
    __shared__ int icol[128][17];

    const unsigned* __restrict__ Wb = (which == 0) ? g_w2 : g_w3;
    const unsigned* __restrict__ Src = useLut ? g_nv : g_act;
    int bn0 = blockIdx.x * 128;
    int bm0 = blockIdx.y * 128;
    int tid = threadIdx.x;
    int ty = tid >> 4, tx = tid & 15;

    if (tid < 27) lut[tid] = g_lutf[tid];
    if (tid < NW) {
        ssel[tid] = useLut ? g_sel[tid] : 0xffffffffu;
        smb[tid]  = useLut ? g_mb[tid]  : 0u;
    }
    __syncthreads();

#pragma unroll
    for (int i = 0; i < 4; i++) {
        int p = tid * 4 + i;
        int r = p >> 3, c4 = (p & 7) << 2;
        uint4 av = *(const uint4*)&Src[(size_t)(bm0 + r) * NW + c4];
        As[c4 + 0][r] = (av.x & ssel[c4 + 0]) ^ smb[c4 + 0];
        As[c4 + 1][r] = (av.y & ssel[c4 + 1]) ^ smb[c4 + 1];
        As[c4 + 2][r] = (av.z & ssel[c4 + 2]) ^ smb[c4 + 2];
        As[c4 + 3][r] = (av.w & ssel[c4 + 3]) ^ smb[c4 + 3];
        uint4 wv = *(const uint4*)&Wb[(size_t)(bn0 + r) * NW + c4];
        Ws[c4 + 0][r] = wv.x; Ws[c4 + 1][r] = wv.y;
        Ws[c4 + 2][r] = wv.z; Ws[c4 + 3][r] = wv.w;
    }
    __syncthreads();

    int acc[8][8];
#pragma unroll
    for (int i = 0; i < 8; i++)
#pragma unroll
        for (int j = 0; j < 8; j++) acc[i][j] = 0;

    for (int w = 0; w < 32; w += 2) {
        unsigned a0[8], b0[8], a1[8], b1[8];
#pragma unroll
        for (int i = 0; i < 8; i++) { a0[i] = As[w][ty * 8 + i]; a1[i] = As[w + 1][ty * 8 + i]; }
#pragma unroll
        for (int j = 0; j < 8; j++) { b0[j] = Ws[w][tx * 8 + j]; b1[j] = Ws[w + 1][tx * 8 + j]; }
#pragma unroll
        for (int i = 0; i < 8; i++)
#pragma unroll
            for (int j = 0; j < 8; j++)
                acc[i][j] += __popc(a0[i] ^ b0[j]) + __popc(a1[i] ^ b1[j]);
    }

    int csum[8];
#pragma unroll
    for (int j = 0; j < 8; j++) csum[j] = 0;
#pragma unroll
    for (int i = 0; i < 8; i++) {
        int rowg = bm0 + ty * 8 + i;
        float4 u0 = *(const float4*)&U[(size_t)rowg * HH + bn0 + tx * 8];
        float4 u1 = *(const float4*)&U[(size_t)rowg * HH + bn0 + tx * 8 + 4];
        float uu[8] = {u0.x, u0.y, u0.z, u0.w, u1.x, u1.y, u1.z, u1.w};
        unsigned byte = 0;
#pragma unroll
        for (int j = 0; j < 8; j++) {
            int cnt = acc[i][j];
            int hs = 512 - cnt;                 // h/2
            int m = (hs < 0) ? -hs : hs;
            if (m > 26) m = 26;
            bool pos = (hs > 0) ^ (uu[j] < lut[m]);
            byte |= (pos ? 1u : 0u) << j;
            csum[j] += pos ? 1 : -1;
        }
        sbits[ty * 8 + i][tx] = (unsigned char)byte;
    }
#pragma unroll
    for (int j = 0; j < 8; j++) icol[tx * 8 + j][ty] = csum[j];
    __syncthreads();

#pragma unroll
    for (int v = 0; v < 2; v++) {
        int wi = tid * 2 + v;
        int row = wi >> 2, w = wi & 3;
        unsigned word = *(const unsigned*)&sbits[row][w * 4];
        g_nv[(size_t)(bm0 + row) * NW + blockIdx.x * 4 + w] = word;
    }
    if (tid < 128) {
        int s = 0;
#pragma unroll
        for (int t = 0; t < 16; t++) s += icol[tid][t];
        g_part[blockIdx.y][bn0 + tid] = (double)s;
    }
}

// Parallelized BN-LUT: 32 blocks x 256 thr; integer partials -> exact.
__global__ void k_lut(const float* __restrict__ gv, const float* __restrict__ bv) {
    __shared__ double sh[8][32];
    int c0 = blockIdx.x * 32;
    int t = threadIdx.x;
    int col = t & 31, slice = t >> 5;
    double s = 0;
    for (int p = slice; p < NPART; p += 8) s += g_part[p][c0 + col];
    sh[slice][col] = s;
    __syncthreads();
    if (t < 32) {
        double tot = 0;
#pragma unroll
        for (int s2 = 0; s2 < 8; s2++) tot += sh[s2][t];
        int c = c0 + t;
        double mu = tot / (double)BB;
        double r = 1.0 / sqrt(1.0 - mu * mu + 1e-5);
        double zp = (( 1.0 - mu) * r) * (double)gv[c] + (double)bv[c];
        double zm = ((-1.0 - mu) * r) * (double)gv[c] + (double)bv[c];
        unsigned pb = __ballot_sync(0xffffffffu, zp > 0.0);
        unsigned mb = __ballot_sync(0xffffffffu, zm > 0.0);
        if (t == 0) {
            g_sel[blockIdx.x] = pb ^ mb;
            g_mb[blockIdx.x]  = mb;
        }
    }
}

// Output layer; applies layer-3 BN-LUT to g_nv on load (replaces k_apply).
__global__ __launch_bounds__(256) void k_out(float* __restrict__ outp) {
    __shared__ unsigned As[256][33];
    __shared__ unsigned W4s[NOUT][NW];
    __shared__ unsigned ssel[NW], smb[NW];
    int r0 = blockIdx.x * 256;
    int t = threadIdx.x;
    if (t < NW) { ssel[t] = g_sel[t]; smb[t] = g_mb[t]; }
    __syncthreads();
#pragma unroll
    for (int i = 0; i < 32; i++) {
        int p = t + 256 * i;
        int wd = p & 31;
        As[p >> 5][wd] = (g_nv[(size_t)r0 * NW + p] & ssel[wd]) ^ smb[wd];
    }
    for (int i = t; i < NOUT * NW; i += 256) ((unsigned*)W4s)[i] = g_w4[i];
    __syncthreads();
#pragma unroll
    for (int o = 0; o < NOUT; o++) {
        int cnt = 0;
#pragma unroll
        for (int w = 0; w < NW; w += 2)
            cnt += __popc(As[t][w] ^ W4s[o][w]) + __popc(As[t][w + 1] ^ W4s[o][w + 1]);
        outp[(size_t)(r0 + t) * NOUT + o] = (float)(HH - 2 * cnt);
    }
}

// ===================================================================
extern "C" void kernel_launch(void* const* d_in, const int* in_sizes, int n_in,
                              void* d_out, int out_size) {
    const float* x  = (const float*)d_in[0];
    const float* u2 = (const float*)d_in[1];
    const float* u3 = (const float*)d_in[2];
    const float* W1 = (const float*)d_in[3];
    const float* W2 = (const float*)d_in[4];
    const float* W3 = (const float*)d_in[5];
    const float* W4 = (const float*)d_in[6];
    const float* g1 = (const float*)d_in[7];
    const float* b1 = (const float*)d_in[8];
    const float* g2 = (const float*)d_in[9];
    const float* b2 = (const float*)d_in[10];
    const float* g3 = (const float*)d_in[11];
    const float* b3 = (const float*)d_in[12];
    float* out = (float*)d_out;

    {
        dim3 tb(32, 8), tg((K1 + 31) / 32, HH / 32);
        k_signW1<<<tg, tb>>>(W1);
    }
    k_packAll<<<(2 * W2_ELEMS + W4_ELEMS + 255) / 256, 256>>>(W2, W3, W4);

    // Layer 1: R13 config -> grid (8, 64)
    dim3 g1grid(HH / 128, BB / 256);
    k_gemm1<<<g1grid, 256>>>(x);
    k_reduce1<<<HH / 64, 64>>>();
    k_pack1<<<(BB * HH) / 256, 256>>>(g1, b1);

    dim3 ggrid(HH / 128, BB / 128);
    // Layer 2: A = g_act (raw), no LUT
    k_bgemm_fused<<<ggrid, 256>>>(0, u2, 0);
    k_lut<<<NW, 256>>>(g2, b2);

    // Layer 3: A = g_nv with layer-2 LUT applied on load
    k_bgemm_fused<<<ggrid, 256>>>(1, u3, 1);
    k_lut<<<NW, 256>>>(g3, b3);

    // Output layer: applies layer-3 LUT on load
    k_out<<<BB / 256, 256>>>(out);
}